// round 16
// baseline (speedup 1.0000x reference)
#include <cuda_runtime.h>
#include <cuda_bf16.h>
#include <math.h>
#include <stdint.h>

// ---------------- problem constants ----------------
constexpr int B_   = 2;
constexpr int T_   = 2048;
constexpr int D_   = 2048;
constexpr int H_   = 16;
constexpr int NOPE = 128;
constexpr int ROPE = 64;
constexpr int QH   = NOPE + ROPE;          // 192
constexpr int QL   = H_ * QH / 4;          // 768
constexpr int KVR  = 512;
constexpr int VD   = 128;
constexpr int MT   = B_ * T_;              // 4096 rows
constexpr int KVN  = H_ * (NOPE + VD);     // 4096
constexpr int QN   = H_ * QH;              // 3072
constexpr int KVC  = KVR + ROPE;           // 576
constexpr int KVCP = 640;                  // padded to 128 multiple
constexpr float EPS = 1e-6f;
constexpr float SCALE = 0.07216878364870322f; // 192^-0.5

// ---------------- static scratch ----------------
__device__ float g_qlora[(size_t)MT * QL];
__device__ float g_q[(size_t)MT * QN];
__device__ float g_kvc[(size_t)MT * KVC];
__device__ float g_cos[(size_t)T_ * 32];
__device__ float g_sin[(size_t)T_ * 32];

__device__ __nv_bfloat16 hid_h[(size_t)MT * D_],  hid_l[(size_t)MT * D_];
__device__ __nv_bfloat16 qlo_h[(size_t)MT * QL],  qlo_l[(size_t)MT * QL];
__device__ __nv_bfloat16 ckv_h[(size_t)MT * KVR], ckv_l[(size_t)MT * KVR];
__device__ __nv_bfloat16 atn_h[(size_t)MT * D_],  atn_l[(size_t)MT * D_];

// attention operands (per-head layouts)
__device__ __nv_bfloat16 aq_h[(size_t)B_ * H_ * T_ * QH], aq_l[(size_t)B_ * H_ * T_ * QH];
__device__ __nv_bfloat16 ak_h[(size_t)B_ * H_ * T_ * QH], ak_l[(size_t)B_ * H_ * T_ * QH];
__device__ __nv_bfloat16 avt_h[(size_t)B_ * H_ * VD * T_], avt_l[(size_t)B_ * H_ * VD * T_];

__device__ __nv_bfloat16 wqaT_h[(size_t)QL * D_],    wqaT_l[(size_t)QL * D_];
__device__ __nv_bfloat16 wqbT_h[(size_t)QN * QL],    wqbT_l[(size_t)QN * QL];
__device__ __nv_bfloat16 wkvaT_h[(size_t)KVCP * D_], wkvaT_l[(size_t)KVCP * D_];
__device__ __nv_bfloat16 wkvbT_h[(size_t)KVN * KVR], wkvbT_l[(size_t)KVN * KVR];
__device__ __nv_bfloat16 woT_h[(size_t)D_ * D_],     woT_l[(size_t)D_ * D_];

// ---------------- PTX helpers (sm_80-class only) ----------------
__device__ __forceinline__ uint32_t smem_u32(const void* p) {
    uint32_t a;
    asm("{ .reg .u64 t; cvta.to.shared.u64 t, %1; cvt.u32.u64 %0, t; }"
        : "=r"(a) : "l"(p));
    return a;
}
__device__ __forceinline__ void split2(float x, __nv_bfloat16& h, __nv_bfloat16& l) {
    h = __float2bfloat16(x);
    l = __float2bfloat16(x - __bfloat162float(h));
}
__device__ __forceinline__ void cp16(uint32_t dst, const void* src) {
    asm volatile("cp.async.cg.shared.global [%0], [%1], 16;"
                 :: "r"(dst), "l"(src) : "memory");
}
__device__ __forceinline__ void ldm4(uint32_t* r, uint32_t a) {
    asm volatile("ldmatrix.sync.aligned.m8n8.x4.shared.b16 {%0,%1,%2,%3}, [%4];"
                 : "=r"(r[0]), "=r"(r[1]), "=r"(r[2]), "=r"(r[3]) : "r"(a));
}
__device__ __forceinline__ void ldm2(uint32_t* r, uint32_t a) {
    asm volatile("ldmatrix.sync.aligned.m8n8.x2.shared.b16 {%0,%1}, [%2];"
                 : "=r"(r[0]), "=r"(r[1]) : "r"(a));
}
__device__ __forceinline__ void mma16816(float* d, const uint32_t* a, const uint32_t* b) {
    asm volatile(
        "mma.sync.aligned.m16n8k16.row.col.f32.bf16.bf16.f32 "
        "{%0,%1,%2,%3}, {%4,%5,%6,%7}, {%8,%9}, {%0,%1,%2,%3};"
        : "+f"(d[0]), "+f"(d[1]), "+f"(d[2]), "+f"(d[3])
        : "r"(a[0]), "r"(a[1]), "r"(a[2]), "r"(a[3]), "r"(b[0]), "r"(b[1]));
}
__device__ __forceinline__ void pack2(float a, float b, uint32_t& hi, uint32_t& lo) {
    __nv_bfloat16 ah = __float2bfloat16(a), bh = __float2bfloat16(b);
    __nv_bfloat16 al = __float2bfloat16(a - __bfloat162float(ah));
    __nv_bfloat16 bl = __float2bfloat16(b - __bfloat162float(bh));
    __nv_bfloat162 vh; vh.x = ah; vh.y = bh;
    __nv_bfloat162 vl; vl.x = al; vl.y = bl;
    hi = *reinterpret_cast<uint32_t*>(&vh);
    lo = *reinterpret_cast<uint32_t*>(&vl);
}

// ---------------- GEMM mainloop shared body (R9-proven: BK=32, 3-stage ring) ----------------
constexpr int GSTAGE = 32768;
constexpr int GSMEM  = 3 * GSTAGE;

#define GEMM_MAINLOOP(Ah, Al, Bh, Bl, K)                                              \
    const int KT = (K) >> 5;                                                          \
    const int lrow0 = tid >> 2, lc0 = tid & 3;                                        \
    const int lrow1 = (tid + 256) >> 2, lc1 = (tid + 256) & 3;                        \
    auto load_stage = [&](int s, int kc) {                                            \
        const uint32_t base = sb0 + (uint32_t)s * GSTAGE;                             \
        {                                                                             \
            const uint32_t off = (uint32_t)(lrow0 * 64 + ((lc0 ^ ((lrow0 & 7) >> 1)) * 16)); \
            const size_t ga = (size_t)(m0 + lrow0) * (K) + kc + lc0 * 8;              \
            const size_t gb = (size_t)(n0 + lrow0) * (K) + kc + lc0 * 8;              \
            cp16(base + off,         (Ah) + ga);                                      \
            cp16(base + 8192 + off,  (Al) + ga);                                      \
            cp16(base + 16384 + off, (Bh) + gb);                                      \
            cp16(base + 24576 + off, (Bl) + gb);                                      \
        }                                                                             \
        {                                                                             \
            const uint32_t off = (uint32_t)(lrow1 * 64 + ((lc1 ^ ((lrow1 & 7) >> 1)) * 16)); \
            const size_t ga = (size_t)(m0 + lrow1) * (K) + kc + lc1 * 8;              \
            const size_t gb = (size_t)(n0 + lrow1) * (K) + kc + lc1 * 8;              \
            cp16(base + off,         (Ah) + ga);                                      \
            cp16(base + 8192 + off,  (Al) + ga);                                      \
            cp16(base + 16384 + off, (Bh) + gb);                                      \
            cp16(base + 24576 + off, (Bl) + gb);                                      \
        }                                                                             \
        asm volatile("cp.async.commit_group;" ::: "memory");                          \
    };                                                                                \
    load_stage(0, 0);                                                                 \
    if (KT > 1) load_stage(1, 32);                                                    \
    for (int kt = 0; kt < KT; kt++) {                                                 \
        const int s = kt % 3;                                                         \
        if (kt + 1 < KT) asm volatile("cp.async.wait_group 1;" ::: "memory");         \
        else             asm volatile("cp.async.wait_group 0;" ::: "memory");         \
        __syncthreads();                                                              \
        if (kt + 2 < KT) load_stage((kt + 2) % 3, (kt + 2) * 32);                     \
        const uint32_t aAh = sb0 + (uint32_t)s * GSTAGE;                              \
        const uint32_t aAl = aAh + 8192;                                              \
        const uint32_t aBh = aAh + 16384;                                             \
        const uint32_t aBl = aAh + 24576;                                             \
        _Pragma("unroll")                                                             \
        for (int ks = 0; ks < 2; ks++) {                                              \
            uint32_t fAh[4][4], fAl[4][4], fBh[4][2], fBl[4][2];                      \
            _Pragma("unroll")                                                         \
            for (int mf = 0; mf < 4; mf++) {                                          \
                const int row = wm * 64 + mf * 16 + (lane & 15);                      \
                const int c = ks * 2 + (lane >> 4);                                   \
                const uint32_t off = (uint32_t)(row * 64 + ((c ^ ((row & 7) >> 1)) * 16)); \
                ldm4(fAh[mf], aAh + off);                                             \
                ldm4(fAl[mf], aAl + off);                                             \
            }                                                                         \
            _Pragma("unroll")                                                         \
            for (int nf = 0; nf < 4; nf++) {                                          \
                const int row = wn * 32 + nf * 8 + (lane & 7);                        \
                const int c = ks * 2 + ((lane >> 3) & 1);                             \
                const uint32_t off = (uint32_t)(row * 64 + ((c ^ ((row & 7) >> 1)) * 16)); \
                ldm2(fBh[nf], aBh + off);                                             \
                ldm2(fBl[nf], aBl + off);                                             \
            }                                                                         \
            _Pragma("unroll")                                                         \
            for (int mf = 0; mf < 4; mf++)                                            \
                _Pragma("unroll")                                                     \
                for (int nf = 0; nf < 4; nf++)                                        \
                    mma16816(acc[mf][nf], fAh[mf], fBh[nf]);                          \
            _Pragma("unroll")                                                         \
            for (int mf = 0; mf < 4; mf++)                                            \
                _Pragma("unroll")                                                     \
                for (int nf = 0; nf < 4; nf++)                                        \
                    mma16816(acc[mf][nf], fAl[mf], fBh[nf]);                          \
            _Pragma("unroll")                                                         \
            for (int mf = 0; mf < 4; mf++)                                            \
                _Pragma("unroll")                                                     \
                for (int nf = 0; nf < 4; nf++)                                        \
                    mma16816(acc[mf][nf], fAh[mf], fBl[nf]);                          \
        }                                                                             \
    }

__global__ __launch_bounds__(256) void mmagemm_kernel(
    const __nv_bfloat16* __restrict__ Ah, const __nv_bfloat16* __restrict__ Al,
    const __nv_bfloat16* __restrict__ Bh, const __nv_bfloat16* __restrict__ Bl,
    float* __restrict__ C, int M, int N, int K)
{
    extern __shared__ char smraw[];
    const uint32_t sb0 = smem_u32(smraw);
    const int tid = threadIdx.x, lane = tid & 31, wid = tid >> 5;
    const int wm = wid >> 2, wn = wid & 3;
    const int m0 = blockIdx.y * 128, n0 = blockIdx.x * 128;

    float acc[4][4][4];
#pragma unroll
    for (int i = 0; i < 4; i++)
#pragma unroll
        for (int j = 0; j < 4; j++)
#pragma unroll
            for (int q = 0; q < 4; q++) acc[i][j][q] = 0.f;

    GEMM_MAINLOOP(Ah, Al, Bh, Bl, K)

    const int g = lane >> 2, tq = lane & 3;
#pragma unroll
    for (int mf = 0; mf < 4; mf++) {
        const int row = m0 + wm * 64 + mf * 16 + g;
#pragma unroll
        for (int nf = 0; nf < 4; nf++) {
            const int col = n0 + wn * 32 + nf * 8 + tq * 2;
            if (col < N) {
                *(float2*)(C + (size_t)row * N + col) =
                    make_float2(acc[mf][nf][0], acc[mf][nf][1]);
                *(float2*)(C + (size_t)(row + 8) * N + col) =
                    make_float2(acc[mf][nf][2], acc[mf][nf][3]);
            }
        }
    }
}

// ---------------- kvb GEMM with fused K-nope + V-transpose epilogues ----------------
// N == KVN, K == KVR. Tiles with (n0 % 256)==0 are K-nope: bf16 hi/lo straight into
// ak layout [B,H,T,192]. Tiles with (n0 % 256)==128 are V: bf16 hi/lo straight into
// transposed avt layout [B,H,VD,T]. No fp32 intermediate at all.
__global__ __launch_bounds__(256) void mmagemm_kv_kernel(
    const __nv_bfloat16* __restrict__ Ah, const __nv_bfloat16* __restrict__ Al,
    const __nv_bfloat16* __restrict__ Bh, const __nv_bfloat16* __restrict__ Bl,
    __nv_bfloat16* __restrict__ Kh, __nv_bfloat16* __restrict__ Kl,
    __nv_bfloat16* __restrict__ Vh, __nv_bfloat16* __restrict__ Vl,
    int M, int N, int K)
{
    extern __shared__ char smraw[];
    const uint32_t sb0 = smem_u32(smraw);
    const int tid = threadIdx.x, lane = tid & 31, wid = tid >> 5;
    const int wm = wid >> 2, wn = wid & 3;
    const int m0 = blockIdx.y * 128, n0 = blockIdx.x * 128;

    float acc[4][4][4];
#pragma unroll
    for (int i = 0; i < 4; i++)
#pragma unroll
        for (int j = 0; j < 4; j++)
#pragma unroll
            for (int q = 0; q < 4; q++) acc[i][j][q] = 0.f;

    GEMM_MAINLOOP(Ah, Al, Bh, Bl, K)

    const int g = lane >> 2, tq = lane & 3;
    const int h = n0 >> 8;
    if ((n0 & 255) == 0) {
        // K-nope tile: emit bf16 hi/lo into attention K layout
#pragma unroll
        for (int mf = 0; mf < 4; mf++) {
            const int row = m0 + wm * 64 + mf * 16 + g;   // row and row+8 share batch
            const int bb = row / T_;
            const int t = row % T_;
#pragma unroll
            for (int nf = 0; nf < 4; nf++) {
                const int d = wn * 32 + nf * 8 + tq * 2;  // 0..127
                uint32_t hi0, lo0, hi1, lo1;
                pack2(acc[mf][nf][0], acc[mf][nf][1], hi0, lo0);
                pack2(acc[mf][nf][2], acc[mf][nf][3], hi1, lo1);
                const size_t o0 = (((size_t)bb * H_ + h) * T_ + t) * QH + d;
                const size_t o1 = (((size_t)bb * H_ + h) * T_ + t + 8) * QH + d;
                *(uint32_t*)(Kh + o0) = hi0; *(uint32_t*)(Kl + o0) = lo0;
                *(uint32_t*)(Kh + o1) = hi1; *(uint32_t*)(Kl + o1) = lo1;
            }
        }
    } else {
        // V tile: emit bf16 hi/lo into TRANSPOSED avt layout [bh][d][t]
#pragma unroll
        for (int mf = 0; mf < 4; mf++) {
            const int row = m0 + wm * 64 + mf * 16 + g;
            const int bb = row / T_;
            const int t = row % T_;
            const size_t bhV = ((size_t)bb * H_ + h) * VD;
#pragma unroll
            for (int nf = 0; nf < 4; nf++) {
                const int d = wn * 32 + nf * 8 + tq * 2;  // 0..127
                __nv_bfloat16 h0, l0, h1, l1, h2, l2, h3, l3;
                split2(acc[mf][nf][0], h0, l0);   // (d,   t)
                split2(acc[mf][nf][1], h1, l1);   // (d+1, t)
                split2(acc[mf][nf][2], h2, l2);   // (d,   t+8)
                split2(acc[mf][nf][3], h3, l3);   // (d+1, t+8)
                const size_t o0 = (bhV + d) * T_ + t;
                const size_t o1 = (bhV + d + 1) * T_ + t;
                Vh[o0] = h0;     Vl[o0] = l0;
                Vh[o1] = h1;     Vl[o1] = l1;
                Vh[o0 + 8] = h2; Vl[o0 + 8] = l2;
                Vh[o1 + 8] = h3; Vl[o1 + 8] = l3;
            }
        }
    }
}

// ---------------- rope tables (256-thread blocks) ----------------
__global__ __launch_bounds__(256) void rope_table_kernel(float* cosv, float* sinv) {
    const int idx = blockIdx.x * 256 + threadIdx.x;   // 0 .. T_*32-1
    const int t = idx >> 5, j = idx & 31;
    const float inv = powf(10000.f, -(float)(2 * j) / (float)ROPE);
    const float fr = (float)t * inv;
    cosv[t * 32 + j] = cosf(fr);
    sinv[t * 32 + j] = sinf(fr);
}

// ---------------- weight transpose + split ----------------
__global__ __launch_bounds__(256) void transpose_split_kernel(
    const float* __restrict__ W, __nv_bfloat16* __restrict__ Th,
    __nv_bfloat16* __restrict__ Tl, int K, int N)
{
    __shared__ float t[32][33];
    const int tx = threadIdx.x & 31, ty = threadIdx.x >> 5;
    const int n0 = blockIdx.x * 32, k0 = blockIdx.y * 32;
#pragma unroll
    for (int i = 0; i < 4; i++) {
        const int k = k0 + ty + i * 8, n = n0 + tx;
        t[ty + i * 8][tx] = (n < N) ? W[(size_t)k * N + n] : 0.f;
    }
    __syncthreads();
#pragma unroll
    for (int i = 0; i < 4; i++) {
        const int n = n0 + ty + i * 8, k = k0 + tx;
        __nv_bfloat16 h, l;
        split2(t[tx][ty + i * 8], h, l);
        Th[(size_t)n * K + k] = h;
        Tl[(size_t)n * K + k] = l;
    }
}

// ---------------- elementwise fp32 -> hi/lo (8 elems/thread) ----------------
__global__ __launch_bounds__(256) void split_kernel(
    const float* __restrict__ X, __nv_bfloat16* __restrict__ H,
    __nv_bfloat16* __restrict__ L, size_t n)
{
    const size_t i = ((size_t)blockIdx.x * blockDim.x + threadIdx.x) * 8;
    if (i + 7 < n) {
        const float4 a = *(const float4*)(X + i);
        const float4 b = *(const float4*)(X + i + 4);
        __nv_bfloat16 hv[8], lv[8];
        split2(a.x, hv[0], lv[0]); split2(a.y, hv[1], lv[1]);
        split2(a.z, hv[2], lv[2]); split2(a.w, hv[3], lv[3]);
        split2(b.x, hv[4], lv[4]); split2(b.y, hv[5], lv[5]);
        split2(b.z, hv[6], lv[6]); split2(b.w, hv[7], lv[7]);
        *(uint4*)(H + i) = *(uint4*)hv;
        *(uint4*)(L + i) = *(uint4*)lv;
    }
}

// ---------------- block reduce ----------------
__device__ __forceinline__ float block_sum(float v) {
    __shared__ float red[8];
    __shared__ float tot;
    const int lane = threadIdx.x & 31, w = threadIdx.x >> 5;
#pragma unroll
    for (int o = 16; o; o >>= 1) v += __shfl_xor_sync(0xffffffffu, v, o);
    if (lane == 0) red[w] = v;
    __syncthreads();
    if (w == 0) {
        float x = (threadIdx.x < (blockDim.x >> 5)) ? red[threadIdx.x] : 0.f;
#pragma unroll
        for (int o = 4; o; o >>= 1) x += __shfl_xor_sync(0xffffffffu, x, o);
        if (threadIdx.x == 0) tot = x;
    }
    __syncthreads();
    return tot;
}

// ---------------- RMSNorm -> hi/lo ----------------
__global__ __launch_bounds__(256) void rms_split_kernel(
    const float* __restrict__ X, const float* __restrict__ g, int ncols,
    __nv_bfloat16* __restrict__ Oh, __nv_bfloat16* __restrict__ Ol)
{
    const int row = blockIdx.x;
    const float* x = X + (size_t)row * ncols;
    float ss = 0.f;
    for (int c = threadIdx.x; c < ncols; c += blockDim.x) { float v = x[c]; ss += v * v; }
    const float total = block_sum(ss);
    const float rs = rsqrtf(total / (float)ncols + EPS);
    for (int c = threadIdx.x; c < ncols; c += blockDim.x) {
        __nv_bfloat16 h, l;
        split2(x[c] * rs * g[c], h, l);
        Oh[(size_t)row * ncols + c] = h;
        Ol[(size_t)row * ncols + c] = l;
    }
}

// ---------------- kv path: rms(c_kv) + rope(k) -> ak rope section directly ----------------
__global__ __launch_bounds__(256) void rmskv_rope_kernel(
    const float* __restrict__ kvc, const float* __restrict__ g_kva_,
    float* __restrict__ out_ckv, __nv_bfloat16* __restrict__ ch,
    __nv_bfloat16* __restrict__ cl, float* __restrict__ out_kr,
    __nv_bfloat16* __restrict__ Kh, __nv_bfloat16* __restrict__ Kl,
    const float* __restrict__ cosv, const float* __restrict__ sinv)
{
    const int row = blockIdx.x;
    const int bb = row / T_, t = row % T_;
    const float* x = kvc + (size_t)row * KVC;
    float ss = 0.f;
    for (int c = threadIdx.x; c < KVR; c += blockDim.x) { float v = x[c]; ss += v * v; }
    const float total = block_sum(ss);
    const float rs = rsqrtf(total / (float)KVR + EPS);
    for (int c = threadIdx.x; c < KVR; c += blockDim.x) {
        const float v = x[c] * rs * g_kva_[c];
        out_ckv[(size_t)row * KVR + c] = v;
        __nv_bfloat16 h, l;
        split2(v, h, l);
        ch[(size_t)row * KVR + c] = h;
        cl[(size_t)row * KVR + c] = l;
    }
    if (threadIdx.x < ROPE) {
        const int d = threadIdx.x;
        const float raw = x[KVR + d];
        out_kr[(size_t)row * ROPE + d] = raw;
        const int j = d & 31;
        const float other = (d < 32) ? -x[KVR + d + 32] : x[KVR + d - 32];
        const float rot = raw * cosv[t * 32 + j] + other * sinv[t * 32 + j];
        __nv_bfloat16 hh, ll;
        split2(rot, hh, ll);
#pragma unroll
        for (int hh_i = 0; hh_i < H_; hh_i++) {
            const size_t o = (((size_t)bb * H_ + hh_i) * T_ + t) * QH + NOPE + d;
            Kh[o] = hh; Kl[o] = ll;
        }
    }
}

// ---------------- q rope + split to [B,H,T,192] (pre-scaled by SCALE) ----------------
__global__ __launch_bounds__(192) void rope_q_split_kernel(
    const float* __restrict__ q, const int* __restrict__ positions,
    __nv_bfloat16* __restrict__ Qh, __nv_bfloat16* __restrict__ Qlo,
    const float* __restrict__ cosv, const float* __restrict__ sinv)
{
    const int row = blockIdx.x;           // b*T + t
    const int h = blockIdx.y;
    const int d = threadIdx.x;            // 0..191
    const int b = row / T_, t = row % T_;
    const int pos = positions[row];
    const float* qr = q + (size_t)row * QN + h * QH;
    float v = qr[d];
    if (d >= NOPE) {
        const int dr = d - NOPE;
        const int j = dr & 31;
        const float other = (dr < 32) ? -qr[d + 32] : qr[d - 32];
        v = v * cosv[pos * 32 + j] + other * sinv[pos * 32 + j];
    }
    v *= SCALE;
    __nv_bfloat16 hh, ll;
    split2(v, hh, ll);
    const size_t o = (((size_t)b * H_ + h) * T_ + t) * QH + d;
    Qh[o] = hh; Qlo[o] = ll;
}

// ---------------- HMMA flash attention (single launch, grid (T/128,H,B)) ----------------
constexpr int AT_SMEM = 212992;

__global__ __launch_bounds__(256) void attn_mma_kernel(
    const __nv_bfloat16* __restrict__ Qh, const __nv_bfloat16* __restrict__ Qlo,
    const __nv_bfloat16* __restrict__ Kh, const __nv_bfloat16* __restrict__ Kl,
    const __nv_bfloat16* __restrict__ Vth, const __nv_bfloat16* __restrict__ Vtl,
    __nv_bfloat16* __restrict__ Oh, __nv_bfloat16* __restrict__ Ol)
{
    extern __shared__ char smraw[];
    const uint32_t sb = smem_u32(smraw);
    const int tid = threadIdx.x, lane = tid & 31, w = tid >> 5;
    const int qt = (int)gridDim.x - 1 - (int)blockIdx.x;
    const int h = blockIdx.y, b = blockIdx.z;
    const int q0 = qt * 128;
    const size_t bhT = ((size_t)b * H_ + h) * T_;
    const size_t bhV = ((size_t)b * H_ + h) * VD;

#pragma unroll
    for (int i = 0; i < 12; i++) {
        const int g = tid + i * 256;
        const int row = g / 24, cg = g % 24;
        const uint32_t dst = (uint32_t)(row * 384 + ((cg ^ (row & 7)) * 16));
        const __nv_bfloat16* src = Qh + (bhT + q0 + row) * QH + cg * 8;
        const __nv_bfloat16* srl = Qlo + (bhT + q0 + row) * QH + cg * 8;
        cp16(sb + 49152 + dst, src);
        cp16(sb + dst, srl);
    }
    asm volatile("cp.async.commit_group;" ::: "memory");
    asm volatile("cp.async.wait_group 0;" ::: "memory");
    __syncthreads();

    uint32_t fQh[12][4];
    {
        const int row = w * 16 + (lane & 15);
#pragma unroll
        for (int kf = 0; kf < 12; kf++) {
            const int cg = kf * 2 + (lane >> 4);
            const uint32_t off = (uint32_t)(row * 384 + ((cg ^ (row & 7)) * 16));
            ldm4(fQh[kf], sb + 49152 + off);
        }
    }
    __syncthreads();

    const int nch = 2 * qt + 2;

    auto load_kv = [&](int buf, int ch) {
        const int s0 = ch * 64;
        const uint32_t kb = sb + 49152 + buf * 49152;
        const uint32_t vb = sb + 147456 + buf * 32768;
#pragma unroll
        for (int i = 0; i < 6; i++) {
            const int g = tid + i * 256;
            const int row = g / 24, cg = g % 24;
            const uint32_t dst = kb + (uint32_t)(row * 384 + ((cg ^ (row & 7)) * 16));
            cp16(dst,          Kh + (bhT + s0 + row) * QH + cg * 8);
            cp16(dst + 24576,  Kl + (bhT + s0 + row) * QH + cg * 8);
        }
#pragma unroll
        for (int i = 0; i < 4; i++) {
            const int g = tid + i * 256;
            const int d = g >> 3, sg = g & 7;
            const uint32_t dst = vb + (uint32_t)(d * 128 + ((sg ^ (d & 7)) * 16));
            cp16(dst,          Vth + (bhV + d) * T_ + s0 + sg * 8);
            cp16(dst + 16384,  Vtl + (bhV + d) * T_ + s0 + sg * 8);
        }
        asm volatile("cp.async.commit_group;" ::: "memory");
    };

    load_kv(0, 0);
    load_kv(1, 1);

    const int gr_a = q0 + w * 16 + (lane >> 2);
    const int gr_b = gr_a + 8;
    float m_a = -1e30f, m_b = -1e30f, l_a = 0.f, l_b = 0.f;
    float oacc[16][4];
#pragma unroll
    for (int i = 0; i < 16; i++)
#pragma unroll
        for (int q = 0; q < 4; q++) oacc[i][q] = 0.f;

    for (int ch = 0; ch < nch; ch++) {
        const int buf = ch & 1;
        const int s0 = ch * 64;
        if (ch + 1 < nch) asm volatile("cp.async.wait_group 1;" ::: "memory");
        else              asm volatile("cp.async.wait_group 0;" ::: "memory");
        __syncthreads();

        const uint32_t kb = sb + 49152 + buf * 49152;
        const uint32_t vb = sb + 147456 + buf * 32768;

        float sc[8][4];
#pragma unroll
        for (int nf = 0; nf < 8; nf++)
#pragma unroll
            for (int q = 0; q < 4; q++) sc[nf][q] = 0.f;

#pragma unroll
        for (int kf = 0; kf < 12; kf++) {
            uint32_t fql[4];
            {
                const int row = w * 16 + (lane & 15);
                const int cg = kf * 2 + (lane >> 4);
                ldm4(fql, sb + (uint32_t)(row * 384 + ((cg ^ (row & 7)) * 16)));
            }
#pragma unroll
            for (int np = 0; np < 4; np++) {
                const int row = np * 16 + (lane & 15);
                const int cg = kf * 2 + (lane >> 4);
                const uint32_t off = (uint32_t)(row * 384 + ((cg ^ (row & 7)) * 16));
                uint32_t rh[4], rl[4];
                ldm4(rh, kb + off);
                ldm4(rl, kb + 24576 + off);
                uint32_t b0h[2] = { rh[0], rh[2] }, b1h[2] = { rh[1], rh[3] };
                uint32_t b0l[2] = { rl[0], rl[2] }, b1l[2] = { rl[1], rl[3] };
                mma16816(sc[2 * np],     fQh[kf], b0h);
                mma16816(sc[2 * np],     fql,     b0h);
                mma16816(sc[2 * np],     fQh[kf], b0l);
                mma16816(sc[2 * np + 1], fQh[kf], b1h);
                mma16816(sc[2 * np + 1], fql,     b1h);
                mma16816(sc[2 * np + 1], fQh[kf], b1l);
            }
        }

        float mxa = -1e30f, mxb = -1e30f;
#pragma unroll
        for (int nf = 0; nf < 8; nf++) {
            const int cb = s0 + nf * 8 + (lane & 3) * 2;
            if (cb     > gr_a) sc[nf][0] = -1e30f;
            if (cb + 1 > gr_a) sc[nf][1] = -1e30f;
            if (cb     > gr_b) sc[nf][2] = -1e30f;
            if (cb + 1 > gr_b) sc[nf][3] = -1e30f;
            mxa = fmaxf(mxa, fmaxf(sc[nf][0], sc[nf][1]));
            mxb = fmaxf(mxb, fmaxf(sc[nf][2], sc[nf][3]));
        }
        mxa = fmaxf(mxa, __shfl_xor_sync(0xffffffffu, mxa, 1));
        mxa = fmaxf(mxa, __shfl_xor_sync(0xffffffffu, mxa, 2));
        mxb = fmaxf(mxb, __shfl_xor_sync(0xffffffffu, mxb, 1));
        mxb = fmaxf(mxb, __shfl_xor_sync(0xffffffffu, mxb, 2));
        const float nma = fmaxf(m_a, mxa), nmb = fmaxf(m_b, mxb);
        const float alpha_a = __expf(m_a - nma), alpha_b = __expf(m_b - nmb);
        m_a = nma; m_b = nmb;

        float suma = 0.f, sumb = 0.f;
        uint32_t Ph[4][4], Pl[4][4];
#pragma unroll
        for (int kf2 = 0; kf2 < 4; kf2++) {
#pragma unroll
            for (int half = 0; half < 2; half++) {
                const int nf = 2 * kf2 + half;
                const float p0 = __expf(sc[nf][0] - nma);
                const float p1 = __expf(sc[nf][1] - nma);
                const float p2 = __expf(sc[nf][2] - nmb);
                const float p3 = __expf(sc[nf][3] - nmb);
                suma += p0 + p1; sumb += p2 + p3;
                pack2(p0, p1, Ph[kf2][half * 2],     Pl[kf2][half * 2]);
                pack2(p2, p3, Ph[kf2][half * 2 + 1], Pl[kf2][half * 2 + 1]);
            }
        }
        suma += __shfl_xor_sync(0xffffffffu, suma, 1);
        suma += __shfl_xor_sync(0xffffffffu, suma, 2);
        sumb += __shfl_xor_sync(0xffffffffu, sumb, 1);
        sumb += __shfl_xor_sync(0xffffffffu, sumb, 2);
        l_a = l_a * alpha_a + suma;
        l_b = l_b * alpha_b + sumb;
#pragma unroll
        for (int nf = 0; nf < 16; nf++) {
            oacc[nf][0] *= alpha_a; oacc[nf][1] *= alpha_a;
            oacc[nf][2] *= alpha_b; oacc[nf][3] *= alpha_b;
        }

#pragma unroll
        for (int kf2 = 0; kf2 < 4; kf2++) {
#pragma unroll
            for (int np = 0; np < 8; np++) {
                const int row = np * 16 + (lane & 15);
                const int cg = kf2 * 2 + (lane >> 4);
                const uint32_t off = (uint32_t)(row * 128 + ((cg ^ (row & 7)) * 16));
                uint32_t rh[4], rl[4];
                ldm4(rh, vb + off);
                ldm4(rl, vb + 16384 + off);
                uint32_t b0h[2] = { rh[0], rh[2] }, b1h[2] = { rh[1], rh[3] };
                uint32_t b0l[2] = { rl[0], rl[2] }, b1l[2] = { rl[1], rl[3] };
                mma16816(oacc[2 * np],     Ph[kf2], b0h);
                mma16816(oacc[2 * np],     Pl[kf2], b0h);
                mma16816(oacc[2 * np],     Ph[kf2], b0l);
                mma16816(oacc[2 * np + 1], Ph[kf2], b1h);
                mma16816(oacc[2 * np + 1], Pl[kf2], b1h);
                mma16816(oacc[2 * np + 1], Ph[kf2], b1l);
            }
        }

        __syncthreads();
        if (ch + 2 < nch) load_kv(buf, ch + 2);
    }

    const float inva = 1.f / l_a, invb = 1.f / l_b;
#pragma unroll
    for (int nf = 0; nf < 16; nf++) {
        const int d = h * VD + nf * 8 + (lane & 3) * 2;
        uint32_t hia, loa, hib, lob;
        pack2(oacc[nf][0] * inva, oacc[nf][1] * inva, hia, loa);
        pack2(oacc[nf][2] * invb, oacc[nf][3] * invb, hib, lob);
        const size_t oa = ((size_t)b * T_ + gr_a) * (size_t)D_ + d;
        const size_t ob = ((size_t)b * T_ + gr_b) * (size_t)D_ + d;
        *(uint32_t*)(Oh + oa) = hia; *(uint32_t*)(Ol + oa) = loa;
        *(uint32_t*)(Oh + ob) = hib; *(uint32_t*)(Ol + ob) = lob;
    }
}

// ---------------- host glue ----------------
template <typename Tp>
static Tp* sym_addr(const void* symbol) {
    void* p = nullptr;
    cudaGetSymbolAddress(&p, symbol);
    return (Tp*)p;
}

// streams/events created at static-init time (no device-memory allocation)
struct StreamPack {
    cudaStream_t s2 = nullptr;
    cudaEvent_t evFork = nullptr, evQ = nullptr, evW = nullptr;
    bool ok = false;
    StreamPack() {
        if (cudaStreamCreateWithFlags(&s2, cudaStreamNonBlocking) == cudaSuccess &&
            cudaEventCreateWithFlags(&evFork, cudaEventDisableTiming) == cudaSuccess &&
            cudaEventCreateWithFlags(&evQ, cudaEventDisableTiming) == cudaSuccess &&
            cudaEventCreateWithFlags(&evW, cudaEventDisableTiming) == cudaSuccess)
            ok = true;
    }
};
static StreamPack g_sp;

extern "C" void kernel_launch(void* const* d_in, const int* in_sizes, int n_in,
                              void* d_out, int out_size)
{
    const float* hidden    = (const float*)d_in[0];
    const int*   positions = (const int*)  d_in[1];
    const float* w_qa  = (const float*)d_in[2];
    const float* g_qa  = (const float*)d_in[3];
    const float* w_qb  = (const float*)d_in[4];
    const float* w_kva = (const float*)d_in[5];
    const float* g_kva = (const float*)d_in[6];
    const float* w_kvb = (const float*)d_in[7];
    const float* w_o   = (const float*)d_in[8];

    float* out      = (float*)d_out;
    float* out_ckv  = out + (size_t)MT * D_;
    float* out_kr   = out_ckv + (size_t)MT * KVR;

    float* p_qlora = sym_addr<float>(g_qlora);
    float* p_q     = sym_addr<float>(g_q);
    float* p_kvc   = sym_addr<float>(g_kvc);
    float* p_cos   = sym_addr<float>(g_cos);
    float* p_sin   = sym_addr<float>(g_sin);

    __nv_bfloat16* p_hid_h = sym_addr<__nv_bfloat16>(hid_h);
    __nv_bfloat16* p_hid_l = sym_addr<__nv_bfloat16>(hid_l);
    __nv_bfloat16* p_qlo_h = sym_addr<__nv_bfloat16>(qlo_h);
    __nv_bfloat16* p_qlo_l = sym_addr<__nv_bfloat16>(qlo_l);
    __nv_bfloat16* p_ckv_h = sym_addr<__nv_bfloat16>(ckv_h);
    __nv_bfloat16* p_ckv_l = sym_addr<__nv_bfloat16>(ckv_l);
    __nv_bfloat16* p_atn_h = sym_addr<__nv_bfloat16>(atn_h);
    __nv_bfloat16* p_atn_l = sym_addr<__nv_bfloat16>(atn_l);
    __nv_bfloat16* p_aq_h = sym_addr<__nv_bfloat16>(aq_h);
    __nv_bfloat16* p_aq_l = sym_addr<__nv_bfloat16>(aq_l);
    __nv_bfloat16* p_ak_h = sym_addr<__nv_bfloat16>(ak_h);
    __nv_bfloat16* p_ak_l = sym_addr<__nv_bfloat16>(ak_l);
    __nv_bfloat16* p_avt_h = sym_addr<__nv_bfloat16>(avt_h);
    __nv_bfloat16* p_avt_l = sym_addr<__nv_bfloat16>(avt_l);
    __nv_bfloat16* p_wqaT_h = sym_addr<__nv_bfloat16>(wqaT_h);
    __nv_bfloat16* p_wqaT_l = sym_addr<__nv_bfloat16>(wqaT_l);
    __nv_bfloat16* p_wqbT_h = sym_addr<__nv_bfloat16>(wqbT_h);
    __nv_bfloat16* p_wqbT_l = sym_addr<__nv_bfloat16>(wqbT_l);
    __nv_bfloat16* p_wkvaT_h = sym_addr<__nv_bfloat16>(wkvaT_h);
    __nv_bfloat16* p_wkvaT_l = sym_addr<__nv_bfloat16>(wkvaT_l);
    __nv_bfloat16* p_wkvbT_h = sym_addr<__nv_bfloat16>(wkvbT_h);
    __nv_bfloat16* p_wkvbT_l = sym_addr<__nv_bfloat16>(wkvbT_l);
    __nv_bfloat16* p_woT_h = sym_addr<__nv_bfloat16>(woT_h);
    __nv_bfloat16* p_woT_l = sym_addr<__nv_bfloat16>(woT_l);

    static bool attr_set = false;
    if (!attr_set) {
        cudaFuncSetAttribute(mmagemm_kernel, cudaFuncAttributeMaxDynamicSharedMemorySize, GSMEM);
        cudaFuncSetAttribute(mmagemm_kv_kernel, cudaFuncAttributeMaxDynamicSharedMemorySize, GSMEM);
        cudaFuncSetAttribute(attn_mma_kernel, cudaFuncAttributeMaxDynamicSharedMemorySize, AT_SMEM);
        attr_set = true;
    }

    const bool dual = g_sp.ok;
    cudaStream_t sQ = dual ? g_sp.s2 : (cudaStream_t)0;

    // ---- shared prologue (default stream) ----
    rope_table_kernel<<<(T_ * 32) / 256, 256>>>(p_cos, p_sin);
    split_kernel<<<(unsigned)(((size_t)MT * D_ / 8 + 255) / 256), 256>>>(
        hidden, p_hid_h, p_hid_l, (size_t)MT * D_);

    if (dual) {
        cudaEventRecord(g_sp.evFork, 0);
        cudaStreamWaitEvent(sQ, g_sp.evFork, 0);
    }

    // ---- q chain (stream sQ); woT transpose appended AFTER rope_q ----
    transpose_split_kernel<<<dim3(QL / 32, D_ / 32), 256, 0, sQ>>>(w_qa, p_wqaT_h, p_wqaT_l, D_, QL);
    transpose_split_kernel<<<dim3(QN / 32, QL / 32), 256, 0, sQ>>>(w_qb, p_wqbT_h, p_wqbT_l, QL, QN);
    mmagemm_kernel<<<dim3(QL / 128, MT / 128), 256, GSMEM, sQ>>>(
        p_hid_h, p_hid_l, p_wqaT_h, p_wqaT_l, p_qlora, MT, QL, D_);
    rms_split_kernel<<<MT, 256, 0, sQ>>>(p_qlora, g_qa, QL, p_qlo_h, p_qlo_l);
    mmagemm_kernel<<<dim3(QN / 128, MT / 128), 256, GSMEM, sQ>>>(
        p_qlo_h, p_qlo_l, p_wqbT_h, p_wqbT_l, p_q, MT, QN, QL);
    rope_q_split_kernel<<<dim3(MT, H_), 192, 0, sQ>>>(p_q, positions, p_aq_h, p_aq_l, p_cos, p_sin);
    if (dual) {
        cudaEventRecord(g_sp.evQ, sQ);    // attention gate: before woT
        transpose_split_kernel<<<dim3(D_ / 32, D_ / 32), 256, 0, sQ>>>(w_o, p_woT_h, p_woT_l, D_, D_);
        cudaEventRecord(g_sp.evW, sQ);    // wo-GEMM gate
    } else {
        transpose_split_kernel<<<dim3(D_ / 32, D_ / 32), 256>>>(w_o, p_woT_h, p_woT_l, D_, D_);
    }

    // ---- kv chain (default stream) ----
    transpose_split_kernel<<<dim3(KVCP / 32, D_ / 32), 256>>>(w_kva, p_wkvaT_h, p_wkvaT_l, D_, KVC);
    transpose_split_kernel<<<dim3(KVN / 32, KVR / 32), 256>>>(w_kvb, p_wkvbT_h, p_wkvbT_l, KVR, KVN);
    mmagemm_kernel<<<dim3(KVCP / 128, MT / 128), 256, GSMEM>>>(
        p_hid_h, p_hid_l, p_wkvaT_h, p_wkvaT_l, p_kvc, MT, KVC, D_);
    // rms + rope; writes roped K (dup x16 heads) straight into ak layout
    rmskv_rope_kernel<<<MT, 256>>>(p_kvc, g_kva, out_ckv, p_ckv_h, p_ckv_l, out_kr,
                                   p_ak_h, p_ak_l, p_cos, p_sin);
    // kvb GEMM with fused K-nope + V-transpose epilogues (no fp32 intermediate)
    mmagemm_kv_kernel<<<dim3(KVN / 128, MT / 128), 256, GSMEM>>>(
        p_ckv_h, p_ckv_l, p_wkvbT_h, p_wkvbT_l,
        p_ak_h, p_ak_l, p_avt_h, p_avt_l, MT, KVN, KVR);

    // join: attention needs q chain (evQ) + kv chain (same stream)
    if (dual) cudaStreamWaitEvent((cudaStream_t)0, g_sp.evQ, 0);

    attn_mma_kernel<<<dim3(T_ / 128, H_, B_), 256, AT_SMEM>>>(
        p_aq_h, p_aq_l, p_ak_h, p_ak_l, p_avt_h, p_avt_l, p_atn_h, p_atn_l);

    if (dual) cudaStreamWaitEvent((cudaStream_t)0, g_sp.evW, 0);  // woT done
    mmagemm_kernel<<<dim3(D_ / 128, MT / 128), 256, GSMEM>>>(
        p_atn_h, p_atn_l, p_woT_h, p_woT_l, out, MT, D_, D_);
}

// round 17
// speedup vs baseline: 1.0377x; 1.0377x over previous
#include <cuda_runtime.h>
#include <cuda_bf16.h>
#include <math.h>
#include <stdint.h>

// ---------------- problem constants ----------------
constexpr int B_   = 2;
constexpr int T_   = 2048;
constexpr int D_   = 2048;
constexpr int H_   = 16;
constexpr int NOPE = 128;
constexpr int ROPE = 64;
constexpr int QH   = NOPE + ROPE;          // 192
constexpr int QL   = H_ * QH / 4;          // 768
constexpr int KVR  = 512;
constexpr int VD   = 128;
constexpr int MT   = B_ * T_;              // 4096 rows
constexpr int KVN  = H_ * (NOPE + VD);     // 4096
constexpr int QN   = H_ * QH;              // 3072
constexpr int KVC  = KVR + ROPE;           // 576
constexpr int KVCP = 640;                  // padded to 128 multiple
constexpr float EPS = 1e-6f;
constexpr float SCALE = 0.07216878364870322f; // 192^-0.5

// ---------------- static scratch ----------------
__device__ float g_qlora[(size_t)MT * QL];
__device__ float g_q[(size_t)MT * QN];
__device__ float g_kvc[(size_t)MT * KVC];
__device__ float g_kv[(size_t)MT * KVN];
__device__ float g_cos[(size_t)T_ * 32];
__device__ float g_sin[(size_t)T_ * 32];
__device__ unsigned int g_ready[32];       // per (b*16 + qt) head-completion counter

__device__ __nv_bfloat16 hid_h[(size_t)MT * D_],  hid_l[(size_t)MT * D_];
__device__ __nv_bfloat16 qlo_h[(size_t)MT * QL],  qlo_l[(size_t)MT * QL];
__device__ __nv_bfloat16 ckv_h[(size_t)MT * KVR], ckv_l[(size_t)MT * KVR];
__device__ __nv_bfloat16 atn_h[(size_t)MT * D_],  atn_l[(size_t)MT * D_];

// attention operands (per-head layouts)
__device__ __nv_bfloat16 aq_h[(size_t)B_ * H_ * T_ * QH], aq_l[(size_t)B_ * H_ * T_ * QH];
__device__ __nv_bfloat16 ak_h[(size_t)B_ * H_ * T_ * QH], ak_l[(size_t)B_ * H_ * T_ * QH];
__device__ __nv_bfloat16 avt_h[(size_t)B_ * H_ * VD * T_], avt_l[(size_t)B_ * H_ * VD * T_];

__device__ __nv_bfloat16 wqaT_h[(size_t)QL * D_],    wqaT_l[(size_t)QL * D_];
__device__ __nv_bfloat16 wqbT_h[(size_t)QN * QL],    wqbT_l[(size_t)QN * QL];
__device__ __nv_bfloat16 wkvaT_h[(size_t)KVCP * D_], wkvaT_l[(size_t)KVCP * D_];
__device__ __nv_bfloat16 wkvbT_h[(size_t)KVN * KVR], wkvbT_l[(size_t)KVN * KVR];
__device__ __nv_bfloat16 woT_h[(size_t)D_ * D_],     woT_l[(size_t)D_ * D_];

// ---------------- PTX helpers (sm_80-class only) ----------------
__device__ __forceinline__ uint32_t smem_u32(const void* p) {
    uint32_t a;
    asm("{ .reg .u64 t; cvta.to.shared.u64 t, %1; cvt.u32.u64 %0, t; }"
        : "=r"(a) : "l"(p));
    return a;
}
__device__ __forceinline__ void split2(float x, __nv_bfloat16& h, __nv_bfloat16& l) {
    h = __float2bfloat16(x);
    l = __float2bfloat16(x - __bfloat162float(h));
}
__device__ __forceinline__ void cp16(uint32_t dst, const void* src) {
    asm volatile("cp.async.cg.shared.global [%0], [%1], 16;"
                 :: "r"(dst), "l"(src) : "memory");
}
__device__ __forceinline__ void ldm4(uint32_t* r, uint32_t a) {
    asm volatile("ldmatrix.sync.aligned.m8n8.x4.shared.b16 {%0,%1,%2,%3}, [%4];"
                 : "=r"(r[0]), "=r"(r[1]), "=r"(r[2]), "=r"(r[3]) : "r"(a));
}
__device__ __forceinline__ void ldm2(uint32_t* r, uint32_t a) {
    asm volatile("ldmatrix.sync.aligned.m8n8.x2.shared.b16 {%0,%1}, [%2];"
                 : "=r"(r[0]), "=r"(r[1]) : "r"(a));
}
__device__ __forceinline__ void mma16816(float* d, const uint32_t* a, const uint32_t* b) {
    asm volatile(
        "mma.sync.aligned.m16n8k16.row.col.f32.bf16.bf16.f32 "
        "{%0,%1,%2,%3}, {%4,%5,%6,%7}, {%8,%9}, {%0,%1,%2,%3};"
        : "+f"(d[0]), "+f"(d[1]), "+f"(d[2]), "+f"(d[3])
        : "r"(a[0]), "r"(a[1]), "r"(a[2]), "r"(a[3]), "r"(b[0]), "r"(b[1]));
}
__device__ __forceinline__ void pack2(float a, float b, uint32_t& hi, uint32_t& lo) {
    __nv_bfloat16 ah = __float2bfloat16(a), bh = __float2bfloat16(b);
    __nv_bfloat16 al = __float2bfloat16(a - __bfloat162float(ah));
    __nv_bfloat16 bl = __float2bfloat16(b - __bfloat162float(bh));
    __nv_bfloat162 vh; vh.x = ah; vh.y = bh;
    __nv_bfloat162 vl; vl.x = al; vl.y = bl;
    hi = *reinterpret_cast<uint32_t*>(&vh);
    lo = *reinterpret_cast<uint32_t*>(&vl);
}

// ---------------- GEMM mainloop shared body (R9-proven: BK=32, 3-stage ring) ----------------
constexpr int GSTAGE = 32768;
constexpr int GSMEM  = 3 * GSTAGE;

#define GEMM_MAINLOOP(Ah, Al, Bh, Bl, K)                                              \
    const int KT = (K) >> 5;                                                          \
    const int lrow0 = tid >> 2, lc0 = tid & 3;                                        \
    const int lrow1 = (tid + 256) >> 2, lc1 = (tid + 256) & 3;                        \
    auto load_stage = [&](int s, int kc) {                                            \
        const uint32_t base = sb0 + (uint32_t)s * GSTAGE;                             \
        {                                                                             \
            const uint32_t off = (uint32_t)(lrow0 * 64 + ((lc0 ^ ((lrow0 & 7) >> 1)) * 16)); \
            const size_t ga = (size_t)(m0 + lrow0) * (K) + kc + lc0 * 8;              \
            const size_t gb = (size_t)(n0 + lrow0) * (K) + kc + lc0 * 8;              \
            cp16(base + off,         (Ah) + ga);                                      \
            cp16(base + 8192 + off,  (Al) + ga);                                      \
            cp16(base + 16384 + off, (Bh) + gb);                                      \
            cp16(base + 24576 + off, (Bl) + gb);                                      \
        }                                                                             \
        {                                                                             \
            const uint32_t off = (uint32_t)(lrow1 * 64 + ((lc1 ^ ((lrow1 & 7) >> 1)) * 16)); \
            const size_t ga = (size_t)(m0 + lrow1) * (K) + kc + lc1 * 8;              \
            const size_t gb = (size_t)(n0 + lrow1) * (K) + kc + lc1 * 8;              \
            cp16(base + off,         (Ah) + ga);                                      \
            cp16(base + 8192 + off,  (Al) + ga);                                      \
            cp16(base + 16384 + off, (Bh) + gb);                                      \
            cp16(base + 24576 + off, (Bl) + gb);                                      \
        }                                                                             \
        asm volatile("cp.async.commit_group;" ::: "memory");                          \
    };                                                                                \
    load_stage(0, 0);                                                                 \
    if (KT > 1) load_stage(1, 32);                                                    \
    for (int kt = 0; kt < KT; kt++) {                                                 \
        const int s = kt % 3;                                                         \
        if (kt + 1 < KT) asm volatile("cp.async.wait_group 1;" ::: "memory");         \
        else             asm volatile("cp.async.wait_group 0;" ::: "memory");         \
        __syncthreads();                                                              \
        if (kt + 2 < KT) load_stage((kt + 2) % 3, (kt + 2) * 32);                     \
        const uint32_t aAh = sb0 + (uint32_t)s * GSTAGE;                              \
        const uint32_t aAl = aAh + 8192;                                              \
        const uint32_t aBh = aAh + 16384;                                             \
        const uint32_t aBl = aAh + 24576;                                             \
        _Pragma("unroll")                                                             \
        for (int ks = 0; ks < 2; ks++) {                                              \
            uint32_t fAh[4][4], fAl[4][4], fBh[4][2], fBl[4][2];                      \
            _Pragma("unroll")                                                         \
            for (int mf = 0; mf < 4; mf++) {                                          \
                const int row = wm * 64 + mf * 16 + (lane & 15);                      \
                const int c = ks * 2 + (lane >> 4);                                   \
                const uint32_t off = (uint32_t)(row * 64 + ((c ^ ((row & 7) >> 1)) * 16)); \
                ldm4(fAh[mf], aAh + off);                                             \
                ldm4(fAl[mf], aAl + off);                                             \
            }                                                                         \
            _Pragma("unroll")                                                         \
            for (int nf = 0; nf < 4; nf++) {                                          \
                const int row = wn * 32 + nf * 8 + (lane & 7);                        \
                const int c = ks * 2 + ((lane >> 3) & 1);                             \
                const uint32_t off = (uint32_t)(row * 64 + ((c ^ ((row & 7) >> 1)) * 16)); \
                ldm2(fBh[nf], aBh + off);                                             \
                ldm2(fBl[nf], aBl + off);                                             \
            }                                                                         \
            _Pragma("unroll")                                                         \
            for (int mf = 0; mf < 4; mf++)                                            \
                _Pragma("unroll")                                                     \
                for (int nf = 0; nf < 4; nf++)                                        \
                    mma16816(acc[mf][nf], fAh[mf], fBh[nf]);                          \
            _Pragma("unroll")                                                         \
            for (int mf = 0; mf < 4; mf++)                                            \
                _Pragma("unroll")                                                     \
                for (int nf = 0; nf < 4; nf++)                                        \
                    mma16816(acc[mf][nf], fAl[mf], fBh[nf]);                          \
            _Pragma("unroll")                                                         \
            for (int mf = 0; mf < 4; mf++)                                            \
                _Pragma("unroll")                                                     \
                for (int nf = 0; nf < 4; nf++)                                        \
                    mma16816(acc[mf][nf], fAh[mf], fBl[nf]);                          \
        }                                                                             \
    }

__global__ __launch_bounds__(256) void mmagemm_kernel(
    const __nv_bfloat16* __restrict__ Ah, const __nv_bfloat16* __restrict__ Al,
    const __nv_bfloat16* __restrict__ Bh, const __nv_bfloat16* __restrict__ Bl,
    float* __restrict__ C, int M, int N, int K)
{
    extern __shared__ char smraw[];
    const uint32_t sb0 = smem_u32(smraw);
    const int tid = threadIdx.x, lane = tid & 31, wid = tid >> 5;
    const int wm = wid >> 2, wn = wid & 3;
    const int m0 = blockIdx.y * 128, n0 = blockIdx.x * 128;

    float acc[4][4][4];
#pragma unroll
    for (int i = 0; i < 4; i++)
#pragma unroll
        for (int j = 0; j < 4; j++)
#pragma unroll
            for (int q = 0; q < 4; q++) acc[i][j][q] = 0.f;

    GEMM_MAINLOOP(Ah, Al, Bh, Bl, K)

    const int g = lane >> 2, tq = lane & 3;
#pragma unroll
    for (int mf = 0; mf < 4; mf++) {
        const int row = m0 + wm * 64 + mf * 16 + g;
#pragma unroll
        for (int nf = 0; nf < 4; nf++) {
            const int col = n0 + wn * 32 + nf * 8 + tq * 2;
            if (col < N) {
                *(float2*)(C + (size_t)row * N + col) =
                    make_float2(acc[mf][nf][0], acc[mf][nf][1]);
                *(float2*)(C + (size_t)(row + 8) * N + col) =
                    make_float2(acc[mf][nf][2], acc[mf][nf][3]);
            }
        }
    }
}

// ---------------- kvb GEMM with fused K-nope epilogue (R14-proven) ----------------
__global__ __launch_bounds__(256) void mmagemm_kv_kernel(
    const __nv_bfloat16* __restrict__ Ah, const __nv_bfloat16* __restrict__ Al,
    const __nv_bfloat16* __restrict__ Bh, const __nv_bfloat16* __restrict__ Bl,
    float* __restrict__ C, __nv_bfloat16* __restrict__ Kh,
    __nv_bfloat16* __restrict__ Kl, int M, int N, int K)
{
    extern __shared__ char smraw[];
    const uint32_t sb0 = smem_u32(smraw);
    const int tid = threadIdx.x, lane = tid & 31, wid = tid >> 5;
    const int wm = wid >> 2, wn = wid & 3;
    const int m0 = blockIdx.y * 128, n0 = blockIdx.x * 128;

    float acc[4][4][4];
#pragma unroll
    for (int i = 0; i < 4; i++)
#pragma unroll
        for (int j = 0; j < 4; j++)
#pragma unroll
            for (int q = 0; q < 4; q++) acc[i][j][q] = 0.f;

    GEMM_MAINLOOP(Ah, Al, Bh, Bl, K)

    const int g = lane >> 2, tq = lane & 3;
    const int h = n0 >> 8;
    if ((n0 & 255) == 0) {
#pragma unroll
        for (int mf = 0; mf < 4; mf++) {
            const int row = m0 + wm * 64 + mf * 16 + g;
            const int bb = row / T_;
            const int t = row % T_;
#pragma unroll
            for (int nf = 0; nf < 4; nf++) {
                const int d = wn * 32 + nf * 8 + tq * 2;
                uint32_t hi0, lo0, hi1, lo1;
                pack2(acc[mf][nf][0], acc[mf][nf][1], hi0, lo0);
                pack2(acc[mf][nf][2], acc[mf][nf][3], hi1, lo1);
                const size_t o0 = (((size_t)bb * H_ + h) * T_ + t) * QH + d;
                const size_t o1 = (((size_t)bb * H_ + h) * T_ + t + 8) * QH + d;
                *(uint32_t*)(Kh + o0) = hi0; *(uint32_t*)(Kl + o0) = lo0;
                *(uint32_t*)(Kh + o1) = hi1; *(uint32_t*)(Kl + o1) = lo1;
            }
        }
    } else {
#pragma unroll
        for (int mf = 0; mf < 4; mf++) {
            const int row = m0 + wm * 64 + mf * 16 + g;
#pragma unroll
            for (int nf = 0; nf < 4; nf++) {
                const int col = n0 + wn * 32 + nf * 8 + tq * 2;
                *(float2*)(C + (size_t)row * N + col) =
                    make_float2(acc[mf][nf][0], acc[mf][nf][1]);
                *(float2*)(C + (size_t)(row + 8) * N + col) =
                    make_float2(acc[mf][nf][2], acc[mf][nf][3]);
            }
        }
    }
}

// ---------------- rope tables ----------------
__global__ __launch_bounds__(256) void rope_table_kernel(float* cosv, float* sinv) {
    const int idx = blockIdx.x * 256 + threadIdx.x;
    const int t = idx >> 5, j = idx & 31;
    const float inv = powf(10000.f, -(float)(2 * j) / (float)ROPE);
    const float fr = (float)t * inv;
    cosv[t * 32 + j] = cosf(fr);
    sinv[t * 32 + j] = sinf(fr);
}

// ---------------- weight transpose + split ----------------
__global__ __launch_bounds__(256) void transpose_split_kernel(
    const float* __restrict__ W, __nv_bfloat16* __restrict__ Th,
    __nv_bfloat16* __restrict__ Tl, int K, int N)
{
    __shared__ float t[32][33];
    const int tx = threadIdx.x & 31, ty = threadIdx.x >> 5;
    const int n0 = blockIdx.x * 32, k0 = blockIdx.y * 32;
#pragma unroll
    for (int i = 0; i < 4; i++) {
        const int k = k0 + ty + i * 8, n = n0 + tx;
        t[ty + i * 8][tx] = (n < N) ? W[(size_t)k * N + n] : 0.f;
    }
    __syncthreads();
#pragma unroll
    for (int i = 0; i < 4; i++) {
        const int n = n0 + ty + i * 8, k = k0 + tx;
        __nv_bfloat16 h, l;
        split2(t[tx][ty + i * 8], h, l);
        Th[(size_t)n * K + k] = h;
        Tl[(size_t)n * K + k] = l;
    }
}

// ---------------- elementwise fp32 -> hi/lo (8 elems/thread) ----------------
__global__ __launch_bounds__(256) void split_kernel(
    const float* __restrict__ X, __nv_bfloat16* __restrict__ H,
    __nv_bfloat16* __restrict__ L, size_t n)
{
    const size_t i = ((size_t)blockIdx.x * blockDim.x + threadIdx.x) * 8;
    if (i + 7 < n) {
        const float4 a = *(const float4*)(X + i);
        const float4 b = *(const float4*)(X + i + 4);
        __nv_bfloat16 hv[8], lv[8];
        split2(a.x, hv[0], lv[0]); split2(a.y, hv[1], lv[1]);
        split2(a.z, hv[2], lv[2]); split2(a.w, hv[3], lv[3]);
        split2(b.x, hv[4], lv[4]); split2(b.y, hv[5], lv[5]);
        split2(b.z, hv[6], lv[6]); split2(b.w, hv[7], lv[7]);
        *(uint4*)(H + i) = *(uint4*)hv;
        *(uint4*)(L + i) = *(uint4*)lv;
    }
}

// ---------------- block reduce ----------------
__device__ __forceinline__ float block_sum(float v) {
    __shared__ float red[8];
    __shared__ float tot;
    const int lane = threadIdx.x & 31, w = threadIdx.x >> 5;
#pragma unroll
    for (int o = 16; o; o >>= 1) v += __shfl_xor_sync(0xffffffffu, v, o);
    if (lane == 0) red[w] = v;
    __syncthreads();
    if (w == 0) {
        float x = (threadIdx.x < (blockDim.x >> 5)) ? red[threadIdx.x] : 0.f;
#pragma unroll
        for (int o = 4; o; o >>= 1) x += __shfl_xor_sync(0xffffffffu, x, o);
        if (threadIdx.x == 0) tot = x;
    }
    __syncthreads();
    return tot;
}

// ---------------- RMSNorm -> hi/lo ----------------
__global__ __launch_bounds__(256) void rms_split_kernel(
    const float* __restrict__ X, const float* __restrict__ g, int ncols,
    __nv_bfloat16* __restrict__ Oh, __nv_bfloat16* __restrict__ Ol)
{
    const int row = blockIdx.x;
    const float* x = X + (size_t)row * ncols;
    float ss = 0.f;
    for (int c = threadIdx.x; c < ncols; c += blockDim.x) { float v = x[c]; ss += v * v; }
    const float total = block_sum(ss);
    const float rs = rsqrtf(total / (float)ncols + EPS);
    for (int c = threadIdx.x; c < ncols; c += blockDim.x) {
        __nv_bfloat16 h, l;
        split2(x[c] * rs * g[c], h, l);
        Oh[(size_t)row * ncols + c] = h;
        Ol[(size_t)row * ncols + c] = l;
    }
}

// ---------------- kv path: rms(c_kv) + rope(k) -> ak rope section directly ----------------
__global__ __launch_bounds__(256) void rmskv_rope_kernel(
    const float* __restrict__ kvc, const float* __restrict__ g_kva_,
    float* __restrict__ out_ckv, __nv_bfloat16* __restrict__ ch,
    __nv_bfloat16* __restrict__ cl, float* __restrict__ out_kr,
    __nv_bfloat16* __restrict__ Kh, __nv_bfloat16* __restrict__ Kl,
    const float* __restrict__ cosv, const float* __restrict__ sinv)
{
    const int row = blockIdx.x;
    const int bb = row / T_, t = row % T_;
    const float* x = kvc + (size_t)row * KVC;
    float ss = 0.f;
    for (int c = threadIdx.x; c < KVR; c += blockDim.x) { float v = x[c]; ss += v * v; }
    const float total = block_sum(ss);
    const float rs = rsqrtf(total / (float)KVR + EPS);
    for (int c = threadIdx.x; c < KVR; c += blockDim.x) {
        const float v = x[c] * rs * g_kva_[c];
        out_ckv[(size_t)row * KVR + c] = v;
        __nv_bfloat16 h, l;
        split2(v, h, l);
        ch[(size_t)row * KVR + c] = h;
        cl[(size_t)row * KVR + c] = l;
    }
    if (threadIdx.x < ROPE) {
        const int d = threadIdx.x;
        const float raw = x[KVR + d];
        out_kr[(size_t)row * ROPE + d] = raw;
        const int j = d & 31;
        const float other = (d < 32) ? -x[KVR + d + 32] : x[KVR + d - 32];
        const float rot = raw * cosv[t * 32 + j] + other * sinv[t * 32 + j];
        __nv_bfloat16 hh, ll;
        split2(rot, hh, ll);
#pragma unroll
        for (int hh_i = 0; hh_i < H_; hh_i++) {
            const size_t o = (((size_t)bb * H_ + hh_i) * T_ + t) * QH + NOPE + d;
            Kh[o] = hh; Kl[o] = ll;
        }
    }
}

// ---------------- q rope + split to [B,H,T,192] (pre-scaled by SCALE) ----------------
__global__ __launch_bounds__(192) void rope_q_split_kernel(
    const float* __restrict__ q, const int* __restrict__ positions,
    __nv_bfloat16* __restrict__ Qh, __nv_bfloat16* __restrict__ Qlo,
    const float* __restrict__ cosv, const float* __restrict__ sinv)
{
    const int row = blockIdx.x;
    const int h = blockIdx.y;
    const int d = threadIdx.x;
    const int b = row / T_, t = row % T_;
    const int pos = positions[row];
    const float* qr = q + (size_t)row * QN + h * QH;
    float v = qr[d];
    if (d >= NOPE) {
        const int dr = d - NOPE;
        const int j = dr & 31;
        const float other = (dr < 32) ? -qr[d + 32] : qr[d - 32];
        v = v * cosv[pos * 32 + j] + other * sinv[pos * 32 + j];
    }
    v *= SCALE;
    __nv_bfloat16 hh, ll;
    split2(v, hh, ll);
    const size_t o = (((size_t)b * H_ + h) * T_ + t) * QH + d;
    Qh[o] = hh; Qlo[o] = ll;
}

// ---------------- v transpose + split to [B,H,128,T] (R14-proven) ----------------
__global__ __launch_bounds__(256) void prep_vt_kernel(
    const float* __restrict__ kv,
    __nv_bfloat16* __restrict__ Vh, __nv_bfloat16* __restrict__ Vl)
{
    __shared__ float s[128 * 66];
    const int bh = blockIdx.x;
    const int t0 = blockIdx.y * 64;
    const int b = bh / H_, h = bh % H_;
    for (int idx = threadIdx.x; idx < 64 * 32; idx += 256) {
        const int t = idx >> 5, c4 = idx & 31;
        const size_t row = (size_t)b * T_ + t0 + t;
        const float4 v = *(const float4*)(kv + row * KVN + h * (NOPE + VD) + NOPE + c4 * 4);
        s[(c4 * 4 + 0) * 66 + t] = v.x;
        s[(c4 * 4 + 1) * 66 + t] = v.y;
        s[(c4 * 4 + 2) * 66 + t] = v.z;
        s[(c4 * 4 + 3) * 66 + t] = v.w;
    }
    __syncthreads();
    for (int idx = threadIdx.x; idx < 128 * 8; idx += 256) {
        const int d = idx >> 3, tg = idx & 7;
        __nv_bfloat16 hv[8], lv[8];
#pragma unroll
        for (int k = 0; k < 8; k++)
            split2(s[d * 66 + tg * 8 + k], hv[k], lv[k]);
        const size_t o = (((size_t)bh) * VD + d) * T_ + t0 + tg * 8;
        *(uint4*)(Vh + o) = *(uint4*)hv;
        *(uint4*)(Vl + o) = *(uint4*)lv;
    }
}

// ---------------- FAT kernel: attention (blocks 0..511) + spin-gated w_o (512..1023) ----
constexpr int AT_SMEM = 212992;

__global__ __launch_bounds__(256) void attn_wo_kernel(
    const __nv_bfloat16* __restrict__ Qh, const __nv_bfloat16* __restrict__ Qlo,
    const __nv_bfloat16* __restrict__ Kh, const __nv_bfloat16* __restrict__ Kl,
    const __nv_bfloat16* __restrict__ Vth, const __nv_bfloat16* __restrict__ Vtl,
    __nv_bfloat16* __restrict__ Oh, __nv_bfloat16* __restrict__ Ol,
    const __nv_bfloat16* __restrict__ Wh, const __nv_bfloat16* __restrict__ Wl,
    float* __restrict__ out)
{
    extern __shared__ char smraw[];
    const int tid = threadIdx.x, lane = tid & 31;
    const int bid = blockIdx.x;

    if (bid < 512) {
        // ================= attention part =================
        const uint32_t sb = smem_u32(smraw);
        const int w = tid >> 5;
        const int qt = 15 - (bid & 15);          // heavy-qt first in placement order
        const int h = (bid >> 4) & 15;
        const int b = bid >> 8;
        const int q0 = qt * 128;
        const size_t bhT = ((size_t)b * H_ + h) * T_;
        const size_t bhV = ((size_t)b * H_ + h) * VD;

#pragma unroll
        for (int i = 0; i < 12; i++) {
            const int g = tid + i * 256;
            const int row = g / 24, cg = g % 24;
            const uint32_t dst = (uint32_t)(row * 384 + ((cg ^ (row & 7)) * 16));
            cp16(sb + 49152 + dst, Qh + (bhT + q0 + row) * QH + cg * 8);
            cp16(sb + dst,          Qlo + (bhT + q0 + row) * QH + cg * 8);
        }
        asm volatile("cp.async.commit_group;" ::: "memory");
        asm volatile("cp.async.wait_group 0;" ::: "memory");
        __syncthreads();

        uint32_t fQh[12][4];
        {
            const int row = w * 16 + (lane & 15);
#pragma unroll
            for (int kf = 0; kf < 12; kf++) {
                const int cg = kf * 2 + (lane >> 4);
                const uint32_t off = (uint32_t)(row * 384 + ((cg ^ (row & 7)) * 16));
                ldm4(fQh[kf], sb + 49152 + off);
            }
        }
        __syncthreads();

        const int nch = 2 * qt + 2;

        auto load_kv = [&](int buf, int ch) {
            const int s0 = ch * 64;
            const uint32_t kb = sb + 49152 + buf * 49152;
            const uint32_t vb = sb + 147456 + buf * 32768;
#pragma unroll
            for (int i = 0; i < 6; i++) {
                const int g = tid + i * 256;
                const int row = g / 24, cg = g % 24;
                const uint32_t dst = kb + (uint32_t)(row * 384 + ((cg ^ (row & 7)) * 16));
                cp16(dst,          Kh + (bhT + s0 + row) * QH + cg * 8);
                cp16(dst + 24576,  Kl + (bhT + s0 + row) * QH + cg * 8);
            }
#pragma unroll
            for (int i = 0; i < 4; i++) {
                const int g = tid + i * 256;
                const int d = g >> 3, sg = g & 7;
                const uint32_t dst = vb + (uint32_t)(d * 128 + ((sg ^ (d & 7)) * 16));
                cp16(dst,          Vth + (bhV + d) * T_ + s0 + sg * 8);
                cp16(dst + 16384,  Vtl + (bhV + d) * T_ + s0 + sg * 8);
            }
            asm volatile("cp.async.commit_group;" ::: "memory");
        };

        load_kv(0, 0);
        load_kv(1, 1);

        const int gr_a = q0 + w * 16 + (lane >> 2);
        const int gr_b = gr_a + 8;
        float m_a = -1e30f, m_b = -1e30f, l_a = 0.f, l_b = 0.f;
        float oacc[16][4];
#pragma unroll
        for (int i = 0; i < 16; i++)
#pragma unroll
            for (int q = 0; q < 4; q++) oacc[i][q] = 0.f;

        for (int ch = 0; ch < nch; ch++) {
            const int buf = ch & 1;
            const int s0 = ch * 64;
            if (ch + 1 < nch) asm volatile("cp.async.wait_group 1;" ::: "memory");
            else              asm volatile("cp.async.wait_group 0;" ::: "memory");
            __syncthreads();

            const uint32_t kb = sb + 49152 + buf * 49152;
            const uint32_t vb = sb + 147456 + buf * 32768;

            float sc[8][4];
#pragma unroll
            for (int nf = 0; nf < 8; nf++)
#pragma unroll
                for (int q = 0; q < 4; q++) sc[nf][q] = 0.f;

#pragma unroll
            for (int kf = 0; kf < 12; kf++) {
                uint32_t fql[4];
                {
                    const int row = w * 16 + (lane & 15);
                    const int cg = kf * 2 + (lane >> 4);
                    ldm4(fql, sb + (uint32_t)(row * 384 + ((cg ^ (row & 7)) * 16)));
                }
#pragma unroll
                for (int np = 0; np < 4; np++) {
                    const int row = np * 16 + (lane & 15);
                    const int cg = kf * 2 + (lane >> 4);
                    const uint32_t off = (uint32_t)(row * 384 + ((cg ^ (row & 7)) * 16));
                    uint32_t rh[4], rl[4];
                    ldm4(rh, kb + off);
                    ldm4(rl, kb + 24576 + off);
                    uint32_t b0h[2] = { rh[0], rh[2] }, b1h[2] = { rh[1], rh[3] };
                    uint32_t b0l[2] = { rl[0], rl[2] }, b1l[2] = { rl[1], rl[3] };
                    mma16816(sc[2 * np],     fQh[kf], b0h);
                    mma16816(sc[2 * np],     fql,     b0h);
                    mma16816(sc[2 * np],     fQh[kf], b0l);
                    mma16816(sc[2 * np + 1], fQh[kf], b1h);
                    mma16816(sc[2 * np + 1], fql,     b1h);
                    mma16816(sc[2 * np + 1], fQh[kf], b1l);
                }
            }

            float mxa = -1e30f, mxb = -1e30f;
#pragma unroll
            for (int nf = 0; nf < 8; nf++) {
                const int cb = s0 + nf * 8 + (lane & 3) * 2;
                if (cb     > gr_a) sc[nf][0] = -1e30f;
                if (cb + 1 > gr_a) sc[nf][1] = -1e30f;
                if (cb     > gr_b) sc[nf][2] = -1e30f;
                if (cb + 1 > gr_b) sc[nf][3] = -1e30f;
                mxa = fmaxf(mxa, fmaxf(sc[nf][0], sc[nf][1]));
                mxb = fmaxf(mxb, fmaxf(sc[nf][2], sc[nf][3]));
            }
            mxa = fmaxf(mxa, __shfl_xor_sync(0xffffffffu, mxa, 1));
            mxa = fmaxf(mxa, __shfl_xor_sync(0xffffffffu, mxa, 2));
            mxb = fmaxf(mxb, __shfl_xor_sync(0xffffffffu, mxb, 1));
            mxb = fmaxf(mxb, __shfl_xor_sync(0xffffffffu, mxb, 2));
            const float nma = fmaxf(m_a, mxa), nmb = fmaxf(m_b, mxb);
            const float alpha_a = __expf(m_a - nma), alpha_b = __expf(m_b - nmb);
            m_a = nma; m_b = nmb;

            float suma = 0.f, sumb = 0.f;
            uint32_t Ph[4][4], Pl[4][4];
#pragma unroll
            for (int kf2 = 0; kf2 < 4; kf2++) {
#pragma unroll
                for (int half = 0; half < 2; half++) {
                    const int nf = 2 * kf2 + half;
                    const float p0 = __expf(sc[nf][0] - nma);
                    const float p1 = __expf(sc[nf][1] - nma);
                    const float p2 = __expf(sc[nf][2] - nmb);
                    const float p3 = __expf(sc[nf][3] - nmb);
                    suma += p0 + p1; sumb += p2 + p3;
                    pack2(p0, p1, Ph[kf2][half * 2],     Pl[kf2][half * 2]);
                    pack2(p2, p3, Ph[kf2][half * 2 + 1], Pl[kf2][half * 2 + 1]);
                }
            }
            suma += __shfl_xor_sync(0xffffffffu, suma, 1);
            suma += __shfl_xor_sync(0xffffffffu, suma, 2);
            sumb += __shfl_xor_sync(0xffffffffu, sumb, 1);
            sumb += __shfl_xor_sync(0xffffffffu, sumb, 2);
            l_a = l_a * alpha_a + suma;
            l_b = l_b * alpha_b + sumb;
#pragma unroll
            for (int nf = 0; nf < 16; nf++) {
                oacc[nf][0] *= alpha_a; oacc[nf][1] *= alpha_a;
                oacc[nf][2] *= alpha_b; oacc[nf][3] *= alpha_b;
            }

#pragma unroll
            for (int kf2 = 0; kf2 < 4; kf2++) {
#pragma unroll
                for (int np = 0; np < 8; np++) {
                    const int row = np * 16 + (lane & 15);
                    const int cg = kf2 * 2 + (lane >> 4);
                    const uint32_t off = (uint32_t)(row * 128 + ((cg ^ (row & 7)) * 16));
                    uint32_t rh[4], rl[4];
                    ldm4(rh, vb + off);
                    ldm4(rl, vb + 16384 + off);
                    uint32_t b0h[2] = { rh[0], rh[2] }, b1h[2] = { rh[1], rh[3] };
                    uint32_t b0l[2] = { rl[0], rl[2] }, b1l[2] = { rl[1], rl[3] };
                    mma16816(oacc[2 * np],     Ph[kf2], b0h);
                    mma16816(oacc[2 * np],     Pl[kf2], b0h);
                    mma16816(oacc[2 * np],     Ph[kf2], b0l);
                    mma16816(oacc[2 * np + 1], Ph[kf2], b1h);
                    mma16816(oacc[2 * np + 1], Pl[kf2], b1h);
                    mma16816(oacc[2 * np + 1], Ph[kf2], b1l);
                }
            }

            __syncthreads();
            if (ch + 2 < nch) load_kv(buf, ch + 2);
        }

        const float inva = 1.f / l_a, invb = 1.f / l_b;
#pragma unroll
        for (int nf = 0; nf < 16; nf++) {
            const int d = h * VD + nf * 8 + (lane & 3) * 2;
            uint32_t hia, loa, hib, lob;
            pack2(oacc[nf][0] * inva, oacc[nf][1] * inva, hia, loa);
            pack2(oacc[nf][2] * invb, oacc[nf][3] * invb, hib, lob);
            const size_t oa = ((size_t)b * T_ + gr_a) * (size_t)D_ + d;
            const size_t ob = ((size_t)b * T_ + gr_b) * (size_t)D_ + d;
            *(uint32_t*)(Oh + oa) = hia; *(uint32_t*)(Ol + oa) = loa;
            *(uint32_t*)(Oh + ob) = hib; *(uint32_t*)(Ol + ob) = lob;
        }

        // release: all stores visible, then signal this (b,qt,h) complete
        __threadfence();
        __syncthreads();
        if (tid == 0) atomicAdd(&g_ready[b * 16 + qt], 1u);
    } else {
        // ================= w_o part (spin-gated) =================
        const uint32_t sb0 = smem_u32(smraw);
        const int wid = tid >> 5;
        const int wm = wid >> 2, wn = wid & 3;
        const int bid2 = bid - 512;
        const int nblk = bid2 & 15;
        const int r = bid2 >> 4;             // 0..31, heavy-qt rows first
        const int qt = 15 - (r >> 1);
        const int b = r & 1;
        const int m0 = (b * 16 + qt) * 128;
        const int n0 = nblk * 128;

        // acquire: wait until all 16 heads of rows [m0, m0+128) are written
        if (tid == 0) {
            while (atomicAdd(&g_ready[b * 16 + qt], 0u) < (unsigned)H_)
                __nanosleep(64);
        }
        __syncthreads();
        __threadfence();

        float acc[4][4][4];
#pragma unroll
        for (int i = 0; i < 4; i++)
#pragma unroll
            for (int j = 0; j < 4; j++)
#pragma unroll
                for (int q = 0; q < 4; q++) acc[i][j][q] = 0.f;

        GEMM_MAINLOOP(Oh, Ol, Wh, Wl, D_)

        const int g = lane >> 2, tq = lane & 3;
#pragma unroll
        for (int mf = 0; mf < 4; mf++) {
            const int row = m0 + wm * 64 + mf * 16 + g;
#pragma unroll
            for (int nf = 0; nf < 4; nf++) {
                const int col = n0 + wn * 32 + nf * 8 + tq * 2;
                *(float2*)(out + (size_t)row * D_ + col) =
                    make_float2(acc[mf][nf][0], acc[mf][nf][1]);
                *(float2*)(out + (size_t)(row + 8) * D_ + col) =
                    make_float2(acc[mf][nf][2], acc[mf][nf][3]);
            }
        }
    }
}

// ---------------- host glue ----------------
template <typename Tp>
static Tp* sym_addr(const void* symbol) {
    void* p = nullptr;
    cudaGetSymbolAddress(&p, symbol);
    return (Tp*)p;
}

// streams/events created at static-init time (no device-memory allocation)
struct StreamPack {
    cudaStream_t s2 = nullptr, s3 = nullptr;
    cudaEvent_t evFork = nullptr, evQ = nullptr, evW = nullptr;
    bool ok = false;
    StreamPack() {
        if (cudaStreamCreateWithFlags(&s2, cudaStreamNonBlocking) == cudaSuccess &&
            cudaStreamCreateWithFlags(&s3, cudaStreamNonBlocking) == cudaSuccess &&
            cudaEventCreateWithFlags(&evFork, cudaEventDisableTiming) == cudaSuccess &&
            cudaEventCreateWithFlags(&evQ, cudaEventDisableTiming) == cudaSuccess &&
            cudaEventCreateWithFlags(&evW, cudaEventDisableTiming) == cudaSuccess)
            ok = true;
    }
};
static StreamPack g_sp;

extern "C" void kernel_launch(void* const* d_in, const int* in_sizes, int n_in,
                              void* d_out, int out_size)
{
    const float* hidden    = (const float*)d_in[0];
    const int*   positions = (const int*)  d_in[1];
    const float* w_qa  = (const float*)d_in[2];
    const float* g_qa  = (const float*)d_in[3];
    const float* w_qb  = (const float*)d_in[4];
    const float* w_kva = (const float*)d_in[5];
    const float* g_kva = (const float*)d_in[6];
    const float* w_kvb = (const float*)d_in[7];
    const float* w_o   = (const float*)d_in[8];

    float* out      = (float*)d_out;
    float* out_ckv  = out + (size_t)MT * D_;
    float* out_kr   = out_ckv + (size_t)MT * KVR;

    float* p_qlora = sym_addr<float>(g_qlora);
    float* p_q     = sym_addr<float>(g_q);
    float* p_kvc   = sym_addr<float>(g_kvc);
    float* p_kv    = sym_addr<float>(g_kv);
    float* p_cos   = sym_addr<float>(g_cos);
    float* p_sin   = sym_addr<float>(g_sin);
    unsigned int* p_ready = sym_addr<unsigned int>(g_ready);

    __nv_bfloat16* p_hid_h = sym_addr<__nv_bfloat16>(hid_h);
    __nv_bfloat16* p_hid_l = sym_addr<__nv_bfloat16>(hid_l);
    __nv_bfloat16* p_qlo_h = sym_addr<__nv_bfloat16>(qlo_h);
    __nv_bfloat16* p_qlo_l = sym_addr<__nv_bfloat16>(qlo_l);
    __nv_bfloat16* p_ckv_h = sym_addr<__nv_bfloat16>(ckv_h);
    __nv_bfloat16* p_ckv_l = sym_addr<__nv_bfloat16>(ckv_l);
    __nv_bfloat16* p_atn_h = sym_addr<__nv_bfloat16>(atn_h);
    __nv_bfloat16* p_atn_l = sym_addr<__nv_bfloat16>(atn_l);
    __nv_bfloat16* p_aq_h = sym_addr<__nv_bfloat16>(aq_h);
    __nv_bfloat16* p_aq_l = sym_addr<__nv_bfloat16>(aq_l);
    __nv_bfloat16* p_ak_h = sym_addr<__nv_bfloat16>(ak_h);
    __nv_bfloat16* p_ak_l = sym_addr<__nv_bfloat16>(ak_l);
    __nv_bfloat16* p_avt_h = sym_addr<__nv_bfloat16>(avt_h);
    __nv_bfloat16* p_avt_l = sym_addr<__nv_bfloat16>(avt_l);
    __nv_bfloat16* p_wqaT_h = sym_addr<__nv_bfloat16>(wqaT_h);
    __nv_bfloat16* p_wqaT_l = sym_addr<__nv_bfloat16>(wqaT_l);
    __nv_bfloat16* p_wqbT_h = sym_addr<__nv_bfloat16>(wqbT_h);
    __nv_bfloat16* p_wqbT_l = sym_addr<__nv_bfloat16>(wqbT_l);
    __nv_bfloat16* p_wkvaT_h = sym_addr<__nv_bfloat16>(wkvaT_h);
    __nv_bfloat16* p_wkvaT_l = sym_addr<__nv_bfloat16>(wkvaT_l);
    __nv_bfloat16* p_wkvbT_h = sym_addr<__nv_bfloat16>(wkvbT_h);
    __nv_bfloat16* p_wkvbT_l = sym_addr<__nv_bfloat16>(wkvbT_l);
    __nv_bfloat16* p_woT_h = sym_addr<__nv_bfloat16>(woT_h);
    __nv_bfloat16* p_woT_l = sym_addr<__nv_bfloat16>(woT_l);

    static bool attr_set = false;
    if (!attr_set) {
        cudaFuncSetAttribute(mmagemm_kernel, cudaFuncAttributeMaxDynamicSharedMemorySize, GSMEM);
        cudaFuncSetAttribute(mmagemm_kv_kernel, cudaFuncAttributeMaxDynamicSharedMemorySize, GSMEM);
        cudaFuncSetAttribute(attn_wo_kernel, cudaFuncAttributeMaxDynamicSharedMemorySize, AT_SMEM);
        attr_set = true;
    }

    const bool dual = g_sp.ok;
    cudaStream_t sQ = dual ? g_sp.s2 : (cudaStream_t)0;
    cudaStream_t sW = dual ? g_sp.s3 : (cudaStream_t)0;

    // ---- prologue (default stream): reset gates, tables, split hidden ----
    cudaMemsetAsync(p_ready, 0, 32 * sizeof(unsigned int), 0);
    rope_table_kernel<<<(T_ * 32) / 256, 256>>>(p_cos, p_sin);
    split_kernel<<<(unsigned)(((size_t)MT * D_ / 8 + 255) / 256), 256>>>(
        hidden, p_hid_h, p_hid_l, (size_t)MT * D_);

    if (dual) {
        cudaEventRecord(g_sp.evFork, 0);
        cudaStreamWaitEvent(sQ, g_sp.evFork, 0);
        cudaStreamWaitEvent(sW, g_sp.evFork, 0);
    }

    // ---- woT transpose on its own stream (done long before the fat kernel) ----
    transpose_split_kernel<<<dim3(D_ / 32, D_ / 32), 256, 0, sW>>>(w_o, p_woT_h, p_woT_l, D_, D_);
    if (dual) cudaEventRecord(g_sp.evW, sW);

    // ---- q chain (stream sQ) ----
    transpose_split_kernel<<<dim3(QL / 32, D_ / 32), 256, 0, sQ>>>(w_qa, p_wqaT_h, p_wqaT_l, D_, QL);
    transpose_split_kernel<<<dim3(QN / 32, QL / 32), 256, 0, sQ>>>(w_qb, p_wqbT_h, p_wqbT_l, QL, QN);
    mmagemm_kernel<<<dim3(QL / 128, MT / 128), 256, GSMEM, sQ>>>(
        p_hid_h, p_hid_l, p_wqaT_h, p_wqaT_l, p_qlora, MT, QL, D_);
    rms_split_kernel<<<MT, 256, 0, sQ>>>(p_qlora, g_qa, QL, p_qlo_h, p_qlo_l);
    mmagemm_kernel<<<dim3(QN / 128, MT / 128), 256, GSMEM, sQ>>>(
        p_qlo_h, p_qlo_l, p_wqbT_h, p_wqbT_l, p_q, MT, QN, QL);
    rope_q_split_kernel<<<dim3(MT, H_), 192, 0, sQ>>>(p_q, positions, p_aq_h, p_aq_l, p_cos, p_sin);
    if (dual) cudaEventRecord(g_sp.evQ, sQ);

    // ---- kv chain (default stream) ----
    transpose_split_kernel<<<dim3(KVCP / 32, D_ / 32), 256>>>(w_kva, p_wkvaT_h, p_wkvaT_l, D_, KVC);
    transpose_split_kernel<<<dim3(KVN / 32, KVR / 32), 256>>>(w_kvb, p_wkvbT_h, p_wkvbT_l, KVR, KVN);
    mmagemm_kernel<<<dim3(KVCP / 128, MT / 128), 256, GSMEM>>>(
        p_hid_h, p_hid_l, p_wkvaT_h, p_wkvaT_l, p_kvc, MT, KVC, D_);
    rmskv_rope_kernel<<<MT, 256>>>(p_kvc, g_kva, out_ckv, p_ckv_h, p_ckv_l, out_kr,
                                   p_ak_h, p_ak_l, p_cos, p_sin);
    mmagemm_kv_kernel<<<dim3(KVN / 128, MT / 128), 256, GSMEM>>>(
        p_ckv_h, p_ckv_l, p_wkvbT_h, p_wkvbT_l, p_kv, p_ak_h, p_ak_l, MT, KVN, KVR);
    prep_vt_kernel<<<dim3(B_ * H_, T_ / 64), 256>>>(p_kv, p_avt_h, p_avt_l);

    // ---- join + fat kernel (attention blocks first, spin-gated w_o behind) ----
    if (dual) {
        cudaStreamWaitEvent((cudaStream_t)0, g_sp.evQ, 0);
        cudaStreamWaitEvent((cudaStream_t)0, g_sp.evW, 0);
    }
    attn_wo_kernel<<<1024, 256, AT_SMEM>>>(
        p_aq_h, p_aq_l, p_ak_h, p_ak_l, p_avt_h, p_avt_l,
        p_atn_h, p_atn_l, p_woT_h, p_woT_l, out);
}